// round 11
// baseline (speedup 1.0000x reference)
#include <cuda_runtime.h>
#include <cuda_bf16.h>
#include <math.h>

// ---------------------------------------------------------------------------
// MAB block, bf16x2 split-precision mma.sync + ldmatrix fragment loads.
// (tcgen05 blocked: harness compiles via compute_103/sm_103 without 'a'.)
// R9: term-major MMA ordering — consecutive mma.sync target distinct
// accumulators (kills the hh->hl->lh RAW chains that capped tensor at 35%).
// ---------------------------------------------------------------------------

#define NQ 2048
#define NK 2048
#define DIM 1024
#define NHEAD 16
#define HD 64
#define PD 512          // u32 pairs per 1024-wide row
#define NKP 1024        // u32 pairs per 2048-wide row (vt)

// fp32 scratch
__device__ float g_q[NQ * DIM];
__device__ float g_o[NQ * DIM];
// bf16 hi/lo planes (u32 = bf16x2 pair, element0 = even index)
__device__ unsigned g_Qihi[NQ * PD],  g_Qilo[NQ * PD];
__device__ unsigned g_Kihi[NK * PD],  g_Kilo[NK * PD];
__device__ unsigned g_wqhi[DIM * PD], g_wqlo[DIM * PD];
__device__ unsigned g_wkhi[DIM * PD], g_wklo[DIM * PD];
__device__ unsigned g_wvhi[DIM * PD], g_wvlo[DIM * PD];
__device__ unsigned g_wohi[DIM * PD], g_wolo[DIM * PD];
__device__ unsigned g_khi[NK * PD],   g_klo[NK * PD];
__device__ unsigned g_vthi[DIM * NKP], g_vtlo[DIM * NKP];
__device__ unsigned g_ohi[NQ * PD],   g_olo[NQ * PD];

// ---------------------------------------------------------------------------
__device__ __forceinline__ void split_pair(float a, float b,
                                           unsigned& hi, unsigned& lo) {
    unsigned h;
    asm("cvt.rn.bf16x2.f32 %0, %1, %2;" : "=r"(h) : "f"(b), "f"(a));
    float ha = __uint_as_float(h << 16);
    float hb = __uint_as_float(h & 0xffff0000u);
    unsigned l;
    float ra = a - ha, rb = b - hb;
    asm("cvt.rn.bf16x2.f32 %0, %1, %2;" : "=r"(l) : "f"(rb), "f"(ra));
    hi = h; lo = l;
}

__device__ __forceinline__ void mma_bf16(float* c, const unsigned* a,
                                         unsigned b0, unsigned b1) {
    asm volatile(
        "mma.sync.aligned.m16n8k16.row.col.f32.bf16.bf16.f32 "
        "{%0,%1,%2,%3},{%4,%5,%6,%7},{%8,%9},{%0,%1,%2,%3};"
        : "+f"(c[0]), "+f"(c[1]), "+f"(c[2]), "+f"(c[3])
        : "r"(a[0]), "r"(a[1]), "r"(a[2]), "r"(a[3]), "r"(b0), "r"(b1));
}

__device__ __forceinline__ void ldsm4(unsigned* r, unsigned addr) {
    asm volatile("ldmatrix.sync.aligned.m8n8.x4.shared.b16 {%0,%1,%2,%3}, [%4];"
        : "=r"(r[0]), "=r"(r[1]), "=r"(r[2]), "=r"(r[3]) : "r"(addr));
}

// e^x via FMA-only exp2 (no MUFU). Valid x <= 0 (clamped at -80).
__device__ __forceinline__ float fexp(float x) {
    float z = fmaxf(x, -80.f) * 1.44269504f;
    float t = z + 12582912.0f;
    int   r = __float_as_int(t) - 0x4B400000;
    float f = z - (t - 12582912.0f);
    float p = 1.0f + f * (0.69314718f + f * (0.24022650f + f * (0.05550411f
                  + f * (0.00961804f + f * 0.00133336f))));
    return __int_as_float(__float_as_int(p) + (r << 23));
}

__device__ __forceinline__ void cp16(unsigned dst, const void* src) {
    asm volatile("cp.async.cg.shared.global [%0], [%1], 16;" :: "r"(dst), "l"(src));
}
#define CP_COMMIT asm volatile("cp.async.commit_group;")
#define CP_WAIT1  asm volatile("cp.async.wait_group 1;")
#define CP_WAIT0  asm volatile("cp.async.wait_group 0;")

// ---------------------------------------------------------------------------
// Fused pack: 8 uniform segments of 512K float2-pairs each.
// ---------------------------------------------------------------------------
#define SEGP 524288
__global__ void pack_all(const float* __restrict__ Q, const float* __restrict__ K,
                         const float* __restrict__ Wq, const float* __restrict__ Wk,
                         const float* __restrict__ Wv, const float* __restrict__ Wo)
{
    int s = blockIdx.y;
    int i = blockIdx.x * blockDim.x + threadIdx.x;
    const float* src;
    unsigned *hi, *lo;
    int off = 0;
    switch (s) {
        case 0: src = Q;  hi = g_Qihi; lo = g_Qilo; break;
        case 1: src = Q;  hi = g_Qihi; lo = g_Qilo; off = SEGP; break;
        case 2: src = K;  hi = g_Kihi; lo = g_Kilo; break;
        case 3: src = K;  hi = g_Kihi; lo = g_Kilo; off = SEGP; break;
        case 4: src = Wq; hi = g_wqhi; lo = g_wqlo; break;
        case 5: src = Wk; hi = g_wkhi; lo = g_wklo; break;
        case 6: src = Wv; hi = g_wvhi; lo = g_wvlo; break;
        default: src = Wo; hi = g_wohi; lo = g_wolo; break;
    }
    float2 v = ((const float2*)src)[off + i];
    unsigned h, l;
    split_pair(v.x, v.y, h, l);
    hi[off + i] = h; lo[off + i] = l;
}

// ---------------------------------------------------------------------------
// GEMM: C[2048,1024] = A @ B^T + bias.  bf16x2 3-mma split, term-major order.
// BM=128 BN=64 BK=32, 8 warps (4m x 2n), warp tile 32x32, ldmatrix loads.
// which=0 qkv fused (z: 0=q,1=k,2=vt), which=1 Wo.
// ---------------------------------------------------------------------------
#define GLD 20
#define ABUFG 2560                  // u32 per A plane (128 rows x 20)
#define BBUFG 1280                  // u32 per B plane (64 rows x 20)
#define STG (2 * ABUFG + 2 * BBUFG) // 7680 u32 per stage
#define GEMM_SMEM (2 * STG * 4)     // 61440 B

__global__ __launch_bounds__(256) void gemm_all(
    const float* __restrict__ bq, const float* __restrict__ bk,
    const float* __restrict__ bv, const float* __restrict__ bo,
    float* __restrict__ outWo, int which)
{
    extern __shared__ unsigned smu[];
    const unsigned sbase = (unsigned)__cvta_generic_to_shared(smu);

    const int tid  = threadIdx.x;
    const int warp = tid >> 5;
    const int lane = tid & 31;
    const int g = lane >> 2;
    const int q = lane & 3;
    const int wm = warp & 3;                   // 4 m-groups of 32 rows
    const int wn = warp >> 2;                  // 2 n-groups of 32 cols
    const int rowBase = blockIdx.y * 128;
    const int colBase = blockIdx.x * 64;

    const int lrowA = lane & 15;
    const int lcolA = (lane >> 4) * 4;
    const int btile = lane >> 4;
    const int browB = lane & 7;
    const int bcolB = ((lane >> 3) & 1) * 4;

    const unsigned *Ahi, *Alo, *Bhi, *Blo;
    const float* bias;
    int mode;                        // 0 fp32, 1 planes, 2 resid+relu, 3 vt planes
    if (which == 1) {
        Ahi = g_ohi; Alo = g_olo; Bhi = g_wohi; Blo = g_wolo;
        bias = bo; mode = 2;
    } else if (blockIdx.z == 0) {
        Ahi = g_Qihi; Alo = g_Qilo; Bhi = g_wqhi; Blo = g_wqlo;
        bias = bq; mode = 0;
    } else if (blockIdx.z == 1) {
        Ahi = g_Kihi; Alo = g_Kilo; Bhi = g_wkhi; Blo = g_wklo;
        bias = bk; mode = 1;
    } else {
        Ahi = g_Kihi; Alo = g_Kilo; Bhi = g_wvhi; Blo = g_wvlo;
        bias = bv; mode = 3;
    }

    auto issue = [&](int kt) {
        unsigned bb = (kt & 1) * STG;
#pragma unroll
        for (int u = 0; u < 4; u++) {
            int e = tid + u * 256;
            int p = e >> 9, row = (e >> 2) & 127, ch = (e & 3) * 4;
            cp16(sbase + (bb + p * ABUFG + row * GLD + ch) * 4,
                 (p ? Alo : Ahi) + (size_t)(rowBase + row) * PD + kt * 16 + ch);
        }
#pragma unroll
        for (int u = 0; u < 2; u++) {
            int e = tid + u * 256;
            int p = e >> 8, row = (e >> 2) & 63, ch = (e & 3) * 4;
            cp16(sbase + (bb + 2 * ABUFG + p * BBUFG + row * GLD + ch) * 4,
                 (p ? Blo : Bhi) + (size_t)(colBase + row) * PD + kt * 16 + ch);
        }
        CP_COMMIT;
    };

    const unsigned aLane = ((wm * 32 + lrowA) * GLD + lcolA) * 4;
    const unsigned bLane = ((wn * 32 + btile * 8 + browB) * GLD + bcolB) * 4;

    float acc[8][4];
#pragma unroll
    for (int i = 0; i < 8; i++)
#pragma unroll
        for (int j = 0; j < 4; j++) acc[i][j] = 0.f;

    issue(0);
    const int NKT = DIM / 32;
    for (int kt = 0; kt < NKT; kt++) {
        if (kt + 1 < NKT) { issue(kt + 1); CP_WAIT1; }
        else              { CP_WAIT0; }
        __syncthreads();
        unsigned bb = (kt & 1) * STG * 4;
        const unsigned aBase = sbase + bb + aLane;
        const unsigned bBase = sbase + bb + 2 * ABUFG * 4 + bLane;

#pragma unroll
        for (int ks = 0; ks < 2; ks++) {
            int pb = ks * 8;
            unsigned ah[2][4], al[2][4];
#pragma unroll
            for (int mt = 0; mt < 2; mt++) {
                unsigned ao = aBase + (mt * 16 * GLD + pb) * 4;
                ldsm4(ah[mt], ao);
                ldsm4(al[mt], ao + ABUFG * 4);
            }
            unsigned bh[2][4], bl[2][4];
#pragma unroll
            for (int j = 0; j < 2; j++) {
                unsigned bo_ = bBase + (j * 16 * GLD + pb) * 4;
                ldsm4(bh[j], bo_);
                ldsm4(bl[j], bo_ + BBUFG * 4);
            }
            // term-major: 8 independent accumulators per pass, no RAW chains
#pragma unroll
            for (int mt = 0; mt < 2; mt++)
#pragma unroll
                for (int nt = 0; nt < 4; nt++)
                    mma_bf16(acc[mt * 4 + nt], ah[mt],
                             bh[nt >> 1][(nt & 1) * 2], bh[nt >> 1][(nt & 1) * 2 + 1]);
#pragma unroll
            for (int mt = 0; mt < 2; mt++)
#pragma unroll
                for (int nt = 0; nt < 4; nt++)
                    mma_bf16(acc[mt * 4 + nt], ah[mt],
                             bl[nt >> 1][(nt & 1) * 2], bl[nt >> 1][(nt & 1) * 2 + 1]);
#pragma unroll
            for (int mt = 0; mt < 2; mt++)
#pragma unroll
                for (int nt = 0; nt < 4; nt++)
                    mma_bf16(acc[mt * 4 + nt], al[mt],
                             bh[nt >> 1][(nt & 1) * 2], bh[nt >> 1][(nt & 1) * 2 + 1]);
        }
        __syncthreads();
    }

    // epilogue
#pragma unroll
    for (int mt = 0; mt < 2; mt++) {
#pragma unroll
        for (int nt = 0; nt < 4; nt++) {
            float* a = acc[mt * 4 + nt];
            int row = rowBase + wm * 32 + mt * 16 + g;
            int col = colBase + wn * 32 + nt * 8 + 2 * q;
            float b0 = bias[col], b1 = bias[col + 1];
#pragma unroll
            for (int half = 0; half < 2; half++) {
                int r = row + half * 8;
                float v0 = a[half * 2 + 0] + b0;
                float v1 = a[half * 2 + 1] + b1;
                if (mode == 3) {
                    float p0 = __shfl_xor_sync(0xffffffffu, v0, 4);
                    float p1 = __shfl_xor_sync(0xffffffffu, v1, 4);
                    if (!(g & 1)) {
                        unsigned h, l;
                        split_pair(v0, p0, h, l);
                        g_vthi[(size_t)col * NKP + r / 2] = h;
                        g_vtlo[(size_t)col * NKP + r / 2] = l;
                        split_pair(v1, p1, h, l);
                        g_vthi[(size_t)(col + 1) * NKP + r / 2] = h;
                        g_vtlo[(size_t)(col + 1) * NKP + r / 2] = l;
                    }
                } else if (mode == 1) {
                    unsigned h, l;
                    split_pair(v0, v1, h, l);
                    g_khi[(size_t)r * PD + col / 2] = h;
                    g_klo[(size_t)r * PD + col / 2] = l;
                } else if (mode == 2) {
                    const float* rp = g_o + (size_t)r * DIM + col;
                    *(float2*)(outWo + (size_t)r * DIM + col) =
                        make_float2(rp[0] + fmaxf(v0, 0.f), rp[1] + fmaxf(v1, 0.f));
                } else {
                    *(float2*)(g_q + (size_t)r * DIM + col) = make_float2(v0, v1);
                }
            }
        }
    }
}

// ---------------------------------------------------------------------------
// Attention: mma.sync bf16x2 + ldmatrix + direct S->P fragment reuse,
// FMA-only exp. R9: term-major MMA ordering in S and PV loops (j-pairs,
// 4 independent accumulators between accumulator reuses).
// ---------------------------------------------------------------------------
#define QREG 8704
#define KLD 36
#define KVT (64 * KLD)
#define ATTN_SMEM ((QREG + 8 * KVT) * 4)   // 108544 B

__global__ __launch_bounds__(256) void attn_bf16x2()
{
    extern __shared__ unsigned smu[];
    const unsigned sbase = (unsigned)__cvta_generic_to_shared(smu);
    float* Qst = (float*)smu;

    const int h  = blockIdx.y;
    const int q0 = blockIdx.x * 128;
    const int c0 = h * HD;
    const int tid  = threadIdx.x;
    const int warp = tid >> 5;
    const int lane = tid & 31;
    const int g = lane >> 2;
    const int q = lane & 3;
    const int wrow = warp * 16;

    const int btile = lane >> 4;
    const int browB = lane & 7;
    const int bcolB = ((lane >> 3) & 1) * 4;
    const unsigned kLane = sbase + (QREG + (btile * 8 + browB) * KLD + bcolB) * 4;

    auto issue = [&](int kb) {
        int buf = kb & 1;
        int k0 = kb * 64;
        const unsigned* srcs[4] = {g_khi, g_klo, g_vthi, g_vtlo};
#pragma unroll
        for (int p = 0; p < 4; p++) {
            unsigned soff = QREG + (buf * 4 + p) * KVT;
#pragma unroll
            for (int u = 0; u < 2; u++) {
                int e = tid + u * 256;
                int row = e >> 3, ch = (e & 7) * 4;
                size_t gidx = (p < 2)
                    ? (size_t)(k0 + row) * PD + h * 32 + ch
                    : (size_t)(c0 + row) * NKP + kb * 32 + ch;
                cp16(sbase + (soff + row * KLD + ch) * 4, srcs[p] + gidx);
            }
        }
        CP_COMMIT;
    };

    issue(0);

#pragma unroll
    for (int u = 0; u < 8; u++) {
        int f = tid + u * 256;
        int r = f >> 4, c4 = (f & 15) << 2;
        float4 a = *(const float4*)(g_q + (size_t)(q0 + r) * DIM + c0 + c4);
        *(float4*)&Qst[r * 68 + c4] = a;
    }
    __syncthreads();

    unsigned qh[4][4], ql[4][4];
#pragma unroll
    for (int s = 0; s < 4; s++) {
        int cb = s * 16 + 2 * q;
        float2 p00 = *(float2*)&Qst[(wrow + g) * 68 + cb];
        float2 p10 = *(float2*)&Qst[(wrow + g + 8) * 68 + cb];
        float2 p01 = *(float2*)&Qst[(wrow + g) * 68 + cb + 8];
        float2 p11 = *(float2*)&Qst[(wrow + g + 8) * 68 + cb + 8];
        split_pair(p00.x, p00.y, qh[s][0], ql[s][0]);
        split_pair(p10.x, p10.y, qh[s][1], ql[s][1]);
        split_pair(p01.x, p01.y, qh[s][2], ql[s][2]);
        split_pair(p11.x, p11.y, qh[s][3], ql[s][3]);
    }
    __syncthreads();

    float m0 = -1e30f, m1 = -1e30f, l0 = 0.f, l1 = 0.f;
    float oacc[8][4];
#pragma unroll
    for (int nt = 0; nt < 8; nt++)
#pragma unroll
        for (int j = 0; j < 4; j++) oacc[nt][j] = 0.f;

    const int NKB = NK / 64;
    for (int kb = 0; kb < NKB; kb++) {
        if (kb + 1 < NKB) { issue(kb + 1); CP_WAIT1; }
        else              { CP_WAIT0; }
        __syncthreads();
        int buf = kb & 1;
        const unsigned kBase = kLane + (buf * 4) * KVT * 4;

        // S = Q K^T, term-major over j-pairs (4 independent accs per pass)
        float sacc[8][4];
#pragma unroll
        for (int nt = 0; nt < 8; nt++)
#pragma unroll
            for (int j = 0; j < 4; j++) sacc[nt][j] = 0.f;
#pragma unroll
        for (int ks = 0; ks < 4; ks++) {
            int pb = ks * 8;
#pragma unroll
            for (int jj = 0; jj < 4; jj += 2) {
                unsigned kh4[2][4], kl4[2][4];
#pragma unroll
                for (int t = 0; t < 2; t++) {
                    unsigned ko = kBase + ((jj + t) * 16 * KLD + pb) * 4;
                    ldsm4(kh4[t], ko);
                    ldsm4(kl4[t], ko + KVT * 4);
                }
#pragma unroll
                for (int t = 0; t < 2; t++) {
                    mma_bf16(sacc[2 * (jj + t)],     qh[ks], kh4[t][0], kh4[t][1]);
                    mma_bf16(sacc[2 * (jj + t) + 1], qh[ks], kh4[t][2], kh4[t][3]);
                }
#pragma unroll
                for (int t = 0; t < 2; t++) {
                    mma_bf16(sacc[2 * (jj + t)],     qh[ks], kl4[t][0], kl4[t][1]);
                    mma_bf16(sacc[2 * (jj + t) + 1], qh[ks], kl4[t][2], kl4[t][3]);
                }
#pragma unroll
                for (int t = 0; t < 2; t++) {
                    mma_bf16(sacc[2 * (jj + t)],     ql[ks], kh4[t][0], kh4[t][1]);
                    mma_bf16(sacc[2 * (jj + t) + 1], ql[ks], kh4[t][2], kh4[t][3]);
                }
            }
        }

        // online softmax (FMA-only exp)
        float mx0 = -1e30f, mx1 = -1e30f;
#pragma unroll
        for (int nt = 0; nt < 8; nt++) {
            mx0 = fmaxf(mx0, fmaxf(sacc[nt][0], sacc[nt][1]));
            mx1 = fmaxf(mx1, fmaxf(sacc[nt][2], sacc[nt][3]));
        }
        mx0 = fmaxf(mx0, __shfl_xor_sync(0xffffffffu, mx0, 1));
        mx0 = fmaxf(mx0, __shfl_xor_sync(0xffffffffu, mx0, 2));
        mx1 = fmaxf(mx1, __shfl_xor_sync(0xffffffffu, mx1, 1));
        mx1 = fmaxf(mx1, __shfl_xor_sync(0xffffffffu, mx1, 2));
        float nm0 = fmaxf(m0, mx0), nm1 = fmaxf(m1, mx1);
        float al0 = fexp(m0 - nm0), al1 = fexp(m1 - nm1);
        m0 = nm0; m1 = nm1;

        float s0 = 0.f, s1 = 0.f;
#pragma unroll
        for (int nt = 0; nt < 8; nt++) {
            sacc[nt][0] = fexp(sacc[nt][0] - nm0);
            sacc[nt][1] = fexp(sacc[nt][1] - nm0);
            sacc[nt][2] = fexp(sacc[nt][2] - nm1);
            sacc[nt][3] = fexp(sacc[nt][3] - nm1);
            s0 += sacc[nt][0] + sacc[nt][1];
            s1 += sacc[nt][2] + sacc[nt][3];
        }
        s0 += __shfl_xor_sync(0xffffffffu, s0, 1);
        s0 += __shfl_xor_sync(0xffffffffu, s0, 2);
        s1 += __shfl_xor_sync(0xffffffffu, s1, 1);
        s1 += __shfl_xor_sync(0xffffffffu, s1, 2);
        l0 = l0 * al0 + s0;
        l1 = l1 * al1 + s1;
#pragma unroll
        for (int nt = 0; nt < 8; nt++) {
            oacc[nt][0] *= al0; oacc[nt][1] *= al0;
            oacc[nt][2] *= al1; oacc[nt][3] *= al1;
        }

        // O += P V, term-major over j-pairs
#pragma unroll
        for (int ks = 0; ks < 4; ks++) {
            unsigned pah[4], pal[4];
            split_pair(sacc[2 * ks][0],     sacc[2 * ks][1],     pah[0], pal[0]);
            split_pair(sacc[2 * ks][2],     sacc[2 * ks][3],     pah[1], pal[1]);
            split_pair(sacc[2 * ks + 1][0], sacc[2 * ks + 1][1], pah[2], pal[2]);
            split_pair(sacc[2 * ks + 1][2], sacc[2 * ks + 1][3], pah[3], pal[3]);
            int pb = ks * 8;
#pragma unroll
            for (int jj = 0; jj < 4; jj += 2) {
                unsigned vh4[2][4], vl4[2][4];
#pragma unroll
                for (int t = 0; t < 2; t++) {
                    unsigned vo = kBase + 2 * KVT * 4 + ((jj + t) * 16 * KLD + pb) * 4;
                    ldsm4(vh4[t], vo);
                    ldsm4(vl4[t], vo + KVT * 4);
                }
#pragma unroll
                for (int t = 0; t < 2; t++) {
                    mma_bf16(oacc[2 * (jj + t)],     pah, vh4[t][0], vh4[t][1]);
                    mma_bf16(oacc[2 * (jj + t) + 1], pah, vh4[t][2], vh4[t][3]);
                }
#pragma unroll
                for (int t = 0; t < 2; t++) {
                    mma_bf16(oacc[2 * (jj + t)],     pah, vl4[t][0], vl4[t][1]);
                    mma_bf16(oacc[2 * (jj + t) + 1], pah, vl4[t][2], vl4[t][3]);
                }
#pragma unroll
                for (int t = 0; t < 2; t++) {
                    mma_bf16(oacc[2 * (jj + t)],     pal, vh4[t][0], vh4[t][1]);
                    mma_bf16(oacc[2 * (jj + t) + 1], pal, vh4[t][2], vh4[t][3]);
                }
            }
        }
        __syncthreads();
    }

    float inv0 = 1.f / (l0 * 32.f);
    float inv1 = 1.f / (l1 * 32.f);
    int n0r = q0 + wrow + g;
    int n1r = n0r + 8;
    int dr0 = h * 128 + (n0r >> 4), dc0 = (n0r & 15) * 64;
    int dr1 = h * 128 + (n1r >> 4), dc1 = (n1r & 15) * 64;
#pragma unroll
    for (int nt = 0; nt < 8; nt++) {
        int c = nt * 8 + 2 * q;
        float2 qr0 = *(const float2*)(g_q + (size_t)n0r * DIM + c0 + c);
        float2 qr1 = *(const float2*)(g_q + (size_t)n1r * DIM + c0 + c);
        float o0x = qr0.x + oacc[nt][0] * inv0;
        float o0y = qr0.y + oacc[nt][1] * inv0;
        float o1x = qr1.x + oacc[nt][2] * inv1;
        float o1y = qr1.y + oacc[nt][3] * inv1;
        *(float2*)(g_o + (size_t)dr0 * DIM + dc0 + c) = make_float2(o0x, o0y);
        *(float2*)(g_o + (size_t)dr1 * DIM + dc1 + c) = make_float2(o1x, o1y);
        unsigned hh, ll;
        split_pair(o0x, o0y, hh, ll);
        g_ohi[(size_t)dr0 * PD + (dc0 + c) / 2] = hh;
        g_olo[(size_t)dr0 * PD + (dc0 + c) / 2] = ll;
        split_pair(o1x, o1y, hh, ll);
        g_ohi[(size_t)dr1 * PD + (dc1 + c) / 2] = hh;
        g_olo[(size_t)dr1 * PD + (dc1 + c) / 2] = ll;
    }
}

// ---------------------------------------------------------------------------
extern "C" void kernel_launch(void* const* d_in, const int* in_sizes, int n_in,
                              void* d_out, int out_size)
{
    const float* Q  = (const float*)d_in[0];
    const float* K  = (const float*)d_in[1];
    const float* Wq = (const float*)d_in[2];
    const float* bq = (const float*)d_in[3];
    const float* Wk = (const float*)d_in[4];
    const float* bk = (const float*)d_in[5];
    const float* Wv = (const float*)d_in[6];
    const float* bv = (const float*)d_in[7];
    const float* Wo = (const float*)d_in[8];
    const float* bo = (const float*)d_in[9];
    float* out = (float*)d_out;

    cudaFuncSetAttribute(gemm_all,    cudaFuncAttributeMaxDynamicSharedMemorySize, GEMM_SMEM);
    cudaFuncSetAttribute(attn_bf16x2, cudaFuncAttributeMaxDynamicSharedMemorySize, ATTN_SMEM);

    pack_all<<<dim3(SEGP / 256, 8), 256>>>(Q, K, Wq, Wk, Wv, Wo);
    gemm_all<<<dim3(DIM / 64, NQ / 128, 3), 256, GEMM_SMEM>>>(bq, bk, bv, bo, out, 0);
    attn_bf16x2<<<dim3(NQ / 128, NHEAD), 256, ATTN_SMEM>>>();
    gemm_all<<<dim3(DIM / 64, NQ / 128, 1), 256, GEMM_SMEM>>>(bq, bk, bv, bo, out, 1);
}

// round 14
// speedup vs baseline: 1.6145x; 1.6145x over previous
#include <cuda_runtime.h>
#include <cuda_bf16.h>
#include <math.h>

// ---------------------------------------------------------------------------
// MAB block, bf16x2 split-precision mma.sync + ldmatrix fragment loads.
// (tcgen05 blocked: harness compiles via compute_103/sm_103 without 'a'.)
// R13 = R12 resubmit (infra failure, never ran): R7 base + 4-stage cp.async
// ring, 2-ahead prefetch, single barrier per iteration. Bit-identical to R7.
// ---------------------------------------------------------------------------

#define NQ 2048
#define NK 2048
#define DIM 1024
#define NHEAD 16
#define HD 64
#define PD 512          // u32 pairs per 1024-wide row
#define NKP 1024        // u32 pairs per 2048-wide row (vt)

// fp32 scratch
__device__ float g_q[NQ * DIM];
__device__ float g_o[NQ * DIM];
// bf16 hi/lo planes (u32 = bf16x2 pair, element0 = even index)
__device__ unsigned g_Qihi[NQ * PD],  g_Qilo[NQ * PD];
__device__ unsigned g_Kihi[NK * PD],  g_Kilo[NK * PD];
__device__ unsigned g_wqhi[DIM * PD], g_wqlo[DIM * PD];
__device__ unsigned g_wkhi[DIM * PD], g_wklo[DIM * PD];
__device__ unsigned g_wvhi[DIM * PD], g_wvlo[DIM * PD];
__device__ unsigned g_wohi[DIM * PD], g_wolo[DIM * PD];
__device__ unsigned g_khi[NK * PD],   g_klo[NK * PD];
__device__ unsigned g_vthi[DIM * NKP], g_vtlo[DIM * NKP];
__device__ unsigned g_ohi[NQ * PD],   g_olo[NQ * PD];

// ---------------------------------------------------------------------------
__device__ __forceinline__ void split_pair(float a, float b,
                                           unsigned& hi, unsigned& lo) {
    unsigned h;
    asm("cvt.rn.bf16x2.f32 %0, %1, %2;" : "=r"(h) : "f"(b), "f"(a));
    float ha = __uint_as_float(h << 16);
    float hb = __uint_as_float(h & 0xffff0000u);
    unsigned l;
    float ra = a - ha, rb = b - hb;
    asm("cvt.rn.bf16x2.f32 %0, %1, %2;" : "=r"(l) : "f"(rb), "f"(ra));
    hi = h; lo = l;
}

__device__ __forceinline__ void mma_bf16(float* c, const unsigned* a,
                                         unsigned b0, unsigned b1) {
    asm volatile(
        "mma.sync.aligned.m16n8k16.row.col.f32.bf16.bf16.f32 "
        "{%0,%1,%2,%3},{%4,%5,%6,%7},{%8,%9},{%0,%1,%2,%3};"
        : "+f"(c[0]), "+f"(c[1]), "+f"(c[2]), "+f"(c[3])
        : "r"(a[0]), "r"(a[1]), "r"(a[2]), "r"(a[3]), "r"(b0), "r"(b1));
}

__device__ __forceinline__ void ldsm4(unsigned* r, unsigned addr) {
    asm volatile("ldmatrix.sync.aligned.m8n8.x4.shared.b16 {%0,%1,%2,%3}, [%4];"
        : "=r"(r[0]), "=r"(r[1]), "=r"(r[2]), "=r"(r[3]) : "r"(addr));
}

// e^x via FMA-only exp2 (no MUFU). Valid x <= 0 (clamped at -80).
__device__ __forceinline__ float fexp(float x) {
    float z = fmaxf(x, -80.f) * 1.44269504f;
    float t = z + 12582912.0f;
    int   r = __float_as_int(t) - 0x4B400000;
    float f = z - (t - 12582912.0f);
    float p = 1.0f + f * (0.69314718f + f * (0.24022650f + f * (0.05550411f
                  + f * (0.00961804f + f * 0.00133336f))));
    return __int_as_float(__float_as_int(p) + (r << 23));
}

__device__ __forceinline__ void cp16(unsigned dst, const void* src) {
    asm volatile("cp.async.cg.shared.global [%0], [%1], 16;" :: "r"(dst), "l"(src));
}
#define CP_COMMIT asm volatile("cp.async.commit_group;")
#define CP_WAIT2  asm volatile("cp.async.wait_group 2;")
#define CP_WAIT1  asm volatile("cp.async.wait_group 1;")
#define CP_WAIT0  asm volatile("cp.async.wait_group 0;")

// ---------------------------------------------------------------------------
// Fused pack: 8 uniform segments of 512K float2-pairs each.
// ---------------------------------------------------------------------------
#define SEGP 524288
__global__ void pack_all(const float* __restrict__ Q, const float* __restrict__ K,
                         const float* __restrict__ Wq, const float* __restrict__ Wk,
                         const float* __restrict__ Wv, const float* __restrict__ Wo)
{
    int s = blockIdx.y;
    int i = blockIdx.x * blockDim.x + threadIdx.x;
    const float* src;
    unsigned *hi, *lo;
    int off = 0;
    switch (s) {
        case 0: src = Q;  hi = g_Qihi; lo = g_Qilo; break;
        case 1: src = Q;  hi = g_Qihi; lo = g_Qilo; off = SEGP; break;
        case 2: src = K;  hi = g_Kihi; lo = g_Kilo; break;
        case 3: src = K;  hi = g_Kihi; lo = g_Kilo; off = SEGP; break;
        case 4: src = Wq; hi = g_wqhi; lo = g_wqlo; break;
        case 5: src = Wk; hi = g_wkhi; lo = g_wklo; break;
        case 6: src = Wv; hi = g_wvhi; lo = g_wvlo; break;
        default: src = Wo; hi = g_wohi; lo = g_wolo; break;
    }
    float2 v = ((const float2*)src)[off + i];
    unsigned h, l;
    split_pair(v.x, v.y, h, l);
    hi[off + i] = h; lo[off + i] = l;
}

// ---------------------------------------------------------------------------
// GEMM: C[2048,1024] = A @ B^T + bias.  bf16x2 3-mma split (R7 order).
// BM=BN=128 BK=32, 8 warps (2m x 4n), warp tile 64x32, ldmatrix loads.
// 4-stage cp.async ring, prefetch 2 ahead, one barrier per iteration.
// which=0 qkv fused (z: 0=q,1=k,2=vt), which=1 Wo.
// ---------------------------------------------------------------------------
#define GLD 20
#define ABUF (128 * GLD)                 // 2560 u32 per plane
#define GSTG (4 * ABUF)                  // 10240 u32 per stage (Ah,Al,Bh,Bl)
#define GEMM_SMEM (4 * GSTG * 4)         // 163840 B

__global__ __launch_bounds__(256) void gemm_all(
    const float* __restrict__ bq, const float* __restrict__ bk,
    const float* __restrict__ bv, const float* __restrict__ bo,
    float* __restrict__ outWo, int which)
{
    extern __shared__ unsigned smu[];
    const unsigned sbase = (unsigned)__cvta_generic_to_shared(smu);

    const int tid  = threadIdx.x;
    const int warp = tid >> 5;
    const int lane = tid & 31;
    const int g = lane >> 2;
    const int q = lane & 3;
    const int wm = warp & 1;
    const int wn = warp >> 1;
    const int rowBase = blockIdx.y * 128;
    const int colBase = blockIdx.x * 128;

    const int lrowA = lane & 15;
    const int lcolA = (lane >> 4) * 4;
    const int btile = lane >> 4;
    const int browB = lane & 7;
    const int bcolB = ((lane >> 3) & 1) * 4;

    const unsigned *Ahi, *Alo, *Bhi, *Blo;
    const float* bias;
    int mode;                        // 0 fp32, 1 planes, 2 resid+relu, 3 vt planes
    if (which == 1) {
        Ahi = g_ohi; Alo = g_olo; Bhi = g_wohi; Blo = g_wolo;
        bias = bo; mode = 2;
    } else if (blockIdx.z == 0) {
        Ahi = g_Qihi; Alo = g_Qilo; Bhi = g_wqhi; Blo = g_wqlo;
        bias = bq; mode = 0;
    } else if (blockIdx.z == 1) {
        Ahi = g_Kihi; Alo = g_Kilo; Bhi = g_wkhi; Blo = g_wklo;
        bias = bk; mode = 1;
    } else {
        Ahi = g_Kihi; Alo = g_Kilo; Bhi = g_wvhi; Blo = g_wvlo;
        bias = bv; mode = 3;
    }

    auto issue = [&](int kt) {
        unsigned bb = (kt & 3) * GSTG;
        const unsigned* srcs[4] = {Ahi, Alo, Bhi, Blo};
#pragma unroll
        for (int p = 0; p < 4; p++) {
            int base = (p < 2) ? rowBase : colBase;
            unsigned soff = bb + p * ABUF;
#pragma unroll
            for (int u = 0; u < 2; u++) {
                int e = tid + u * 256;
                int row = e >> 2, ch = (e & 3) * 4;
                cp16(sbase + (soff + row * GLD + ch) * 4,
                     srcs[p] + (size_t)(base + row) * PD + kt * 16 + ch);
            }
        }
        CP_COMMIT;
    };

    const unsigned aLane = ((wm * 64 + lrowA) * GLD + lcolA) * 4;
    const unsigned bLane = ((wn * 32 + btile * 8 + browB) * GLD + bcolB) * 4;

    float acc[16][4];
#pragma unroll
    for (int i = 0; i < 16; i++)
#pragma unroll
        for (int j = 0; j < 4; j++) acc[i][j] = 0.f;

    issue(0);
    issue(1);
    const int NKT = DIM / 32;
    for (int kt = 0; kt < NKT; kt++) {
        if (kt + 2 < NKT) { issue(kt + 2); CP_WAIT2; }
        else if (kt + 1 < NKT) { CP_WAIT1; }
        else { CP_WAIT0; }
        __syncthreads();
        unsigned bb = (kt & 3) * GSTG * 4;
        const unsigned aBase = sbase + bb + aLane;
        const unsigned bBase = sbase + bb + 2 * ABUF * 4 + bLane;

#pragma unroll
        for (int ks = 0; ks < 2; ks++) {
            int pb = ks * 8;
            unsigned ah[4][4], al[4][4];
#pragma unroll
            for (int mt = 0; mt < 4; mt++) {
                unsigned ao = aBase + (mt * 16 * GLD + pb) * 4;
                ldsm4(ah[mt], ao);
                ldsm4(al[mt], ao + ABUF * 4);
            }
            unsigned bh[2][4], bl[2][4];
#pragma unroll
            for (int j = 0; j < 2; j++) {
                unsigned bo_ = bBase + (j * 16 * GLD + pb) * 4;
                ldsm4(bh[j], bo_);
                ldsm4(bl[j], bo_ + ABUF * 4);
            }
#pragma unroll
            for (int mt = 0; mt < 4; mt++)
#pragma unroll
                for (int nt = 0; nt < 4; nt++) {
                    unsigned b0h = bh[nt >> 1][(nt & 1) * 2];
                    unsigned b1h = bh[nt >> 1][(nt & 1) * 2 + 1];
                    unsigned b0l = bl[nt >> 1][(nt & 1) * 2];
                    unsigned b1l = bl[nt >> 1][(nt & 1) * 2 + 1];
                    mma_bf16(acc[mt * 4 + nt], ah[mt], b0h, b1h);
                    mma_bf16(acc[mt * 4 + nt], ah[mt], b0l, b1l);
                    mma_bf16(acc[mt * 4 + nt], al[mt], b0h, b1h);
                }
        }
        // no trailing barrier: buffer (kt mod 4) is only rewritten at kt+4,
        // separated from these reads by the top barriers of kt+1 and kt+2.
    }

    // epilogue
#pragma unroll
    for (int mt = 0; mt < 4; mt++) {
#pragma unroll
        for (int nt = 0; nt < 4; nt++) {
            float* a = acc[mt * 4 + nt];
            int row = rowBase + wm * 64 + mt * 16 + g;
            int col = colBase + wn * 32 + nt * 8 + 2 * q;
            float b0 = bias[col], b1 = bias[col + 1];
#pragma unroll
            for (int half = 0; half < 2; half++) {
                int r = row + half * 8;
                float v0 = a[half * 2 + 0] + b0;
                float v1 = a[half * 2 + 1] + b1;
                if (mode == 3) {
                    float p0 = __shfl_xor_sync(0xffffffffu, v0, 4);
                    float p1 = __shfl_xor_sync(0xffffffffu, v1, 4);
                    if (!(g & 1)) {
                        unsigned h, l;
                        split_pair(v0, p0, h, l);
                        g_vthi[(size_t)col * NKP + r / 2] = h;
                        g_vtlo[(size_t)col * NKP + r / 2] = l;
                        split_pair(v1, p1, h, l);
                        g_vthi[(size_t)(col + 1) * NKP + r / 2] = h;
                        g_vtlo[(size_t)(col + 1) * NKP + r / 2] = l;
                    }
                } else if (mode == 1) {
                    unsigned h, l;
                    split_pair(v0, v1, h, l);
                    g_khi[(size_t)r * PD + col / 2] = h;
                    g_klo[(size_t)r * PD + col / 2] = l;
                } else if (mode == 2) {
                    const float* rp = g_o + (size_t)r * DIM + col;
                    *(float2*)(outWo + (size_t)r * DIM + col) =
                        make_float2(rp[0] + fmaxf(v0, 0.f), rp[1] + fmaxf(v1, 0.f));
                } else {
                    *(float2*)(g_q + (size_t)r * DIM + col) = make_float2(v0, v1);
                }
            }
        }
    }
}

// ---------------------------------------------------------------------------
// Attention: mma.sync bf16x2 + ldmatrix + direct S->P fragment reuse,
// FMA-only exp (R7 math). 4-stage KV ring, prefetch 2 ahead, one barrier
// per iteration.
// ---------------------------------------------------------------------------
#define QREG 8704
#define KLD 36
#define KVT (64 * KLD)                       // 2304 u32 per plane tile
#define ASTG (4 * KVT)                       // stage = Kh,Kl,Vh,Vl
#define ATTN_SMEM ((QREG + 4 * ASTG) * 4)    // 182272 B

__global__ __launch_bounds__(256) void attn_bf16x2()
{
    extern __shared__ unsigned smu[];
    const unsigned sbase = (unsigned)__cvta_generic_to_shared(smu);
    float* Qst = (float*)smu;

    const int h  = blockIdx.y;
    const int q0 = blockIdx.x * 128;
    const int c0 = h * HD;
    const int tid  = threadIdx.x;
    const int warp = tid >> 5;
    const int lane = tid & 31;
    const int g = lane >> 2;
    const int q = lane & 3;
    const int wrow = warp * 16;

    const int btile = lane >> 4;
    const int browB = lane & 7;
    const int bcolB = ((lane >> 3) & 1) * 4;
    const unsigned kLane = sbase + (QREG + (btile * 8 + browB) * KLD + bcolB) * 4;

    auto issue = [&](int kb) {
        int buf = kb & 3;
        int k0 = kb * 64;
        const unsigned* srcs[4] = {g_khi, g_klo, g_vthi, g_vtlo};
#pragma unroll
        for (int p = 0; p < 4; p++) {
            unsigned soff = QREG + buf * ASTG + p * KVT;
#pragma unroll
            for (int u = 0; u < 2; u++) {
                int e = tid + u * 256;
                int row = e >> 3, ch = (e & 7) * 4;
                size_t gidx = (p < 2)
                    ? (size_t)(k0 + row) * PD + h * 32 + ch
                    : (size_t)(c0 + row) * NKP + kb * 32 + ch;
                cp16(sbase + (soff + row * KLD + ch) * 4, srcs[p] + gidx);
            }
        }
        CP_COMMIT;
    };

    issue(0);
    issue(1);

#pragma unroll
    for (int u = 0; u < 8; u++) {
        int f = tid + u * 256;
        int r = f >> 4, c4 = (f & 15) << 2;
        float4 a = *(const float4*)(g_q + (size_t)(q0 + r) * DIM + c0 + c4);
        *(float4*)&Qst[r * 68 + c4] = a;
    }
    __syncthreads();

    unsigned qh[4][4], ql[4][4];
#pragma unroll
    for (int s = 0; s < 4; s++) {
        int cb = s * 16 + 2 * q;
        float2 p00 = *(float2*)&Qst[(wrow + g) * 68 + cb];
        float2 p10 = *(float2*)&Qst[(wrow + g + 8) * 68 + cb];
        float2 p01 = *(float2*)&Qst[(wrow + g) * 68 + cb + 8];
        float2 p11 = *(float2*)&Qst[(wrow + g + 8) * 68 + cb + 8];
        split_pair(p00.x, p00.y, qh[s][0], ql[s][0]);
        split_pair(p10.x, p10.y, qh[s][1], ql[s][1]);
        split_pair(p01.x, p01.y, qh[s][2], ql[s][2]);
        split_pair(p11.x, p11.y, qh[s][3], ql[s][3]);
    }
    __syncthreads();

    float m0 = -1e30f, m1 = -1e30f, l0 = 0.f, l1 = 0.f;
    float oacc[8][4];
#pragma unroll
    for (int nt = 0; nt < 8; nt++)
#pragma unroll
        for (int j = 0; j < 4; j++) oacc[nt][j] = 0.f;

    const int NKB = NK / 64;
    for (int kb = 0; kb < NKB; kb++) {
        if (kb + 2 < NKB) { issue(kb + 2); CP_WAIT2; }
        else if (kb + 1 < NKB) { CP_WAIT1; }
        else { CP_WAIT0; }
        __syncthreads();
        const unsigned kBase = kLane + (kb & 3) * ASTG * 4;

        // S = Q K^T (R7 order)
        float sacc[8][4];
#pragma unroll
        for (int nt = 0; nt < 8; nt++)
#pragma unroll
            for (int j = 0; j < 4; j++) sacc[nt][j] = 0.f;
#pragma unroll
        for (int ks = 0; ks < 4; ks++) {
            int pb = ks * 8;
#pragma unroll
            for (int j = 0; j < 4; j++) {
                unsigned kh4[4], kl4[4];
                unsigned ko = kBase + (j * 16 * KLD + pb) * 4;
                ldsm4(kh4, ko);
                ldsm4(kl4, ko + KVT * 4);
                mma_bf16(sacc[2 * j],     qh[ks], kh4[0], kh4[1]);
                mma_bf16(sacc[2 * j],     qh[ks], kl4[0], kl4[1]);
                mma_bf16(sacc[2 * j],     ql[ks], kh4[0], kh4[1]);
                mma_bf16(sacc[2 * j + 1], qh[ks], kh4[2], kh4[3]);
                mma_bf16(sacc[2 * j + 1], qh[ks], kl4[2], kl4[3]);
                mma_bf16(sacc[2 * j + 1], ql[ks], kh4[2], kh4[3]);
            }
        }

        // online softmax (FMA-only exp)
        float mx0 = -1e30f, mx1 = -1e30f;
#pragma unroll
        for (int nt = 0; nt < 8; nt++) {
            mx0 = fmaxf(mx0, fmaxf(sacc[nt][0], sacc[nt][1]));
            mx1 = fmaxf(mx1, fmaxf(sacc[nt][2], sacc[nt][3]));
        }
        mx0 = fmaxf(mx0, __shfl_xor_sync(0xffffffffu, mx0, 1));
        mx0 = fmaxf(mx0, __shfl_xor_sync(0xffffffffu, mx0, 2));
        mx1 = fmaxf(mx1, __shfl_xor_sync(0xffffffffu, mx1, 1));
        mx1 = fmaxf(mx1, __shfl_xor_sync(0xffffffffu, mx1, 2));
        float nm0 = fmaxf(m0, mx0), nm1 = fmaxf(m1, mx1);
        float al0 = fexp(m0 - nm0), al1 = fexp(m1 - nm1);
        m0 = nm0; m1 = nm1;

        float s0 = 0.f, s1 = 0.f;
#pragma unroll
        for (int nt = 0; nt < 8; nt++) {
            sacc[nt][0] = fexp(sacc[nt][0] - nm0);
            sacc[nt][1] = fexp(sacc[nt][1] - nm0);
            sacc[nt][2] = fexp(sacc[nt][2] - nm1);
            sacc[nt][3] = fexp(sacc[nt][3] - nm1);
            s0 += sacc[nt][0] + sacc[nt][1];
            s1 += sacc[nt][2] + sacc[nt][3];
        }
        s0 += __shfl_xor_sync(0xffffffffu, s0, 1);
        s0 += __shfl_xor_sync(0xffffffffu, s0, 2);
        s1 += __shfl_xor_sync(0xffffffffu, s1, 1);
        s1 += __shfl_xor_sync(0xffffffffu, s1, 2);
        l0 = l0 * al0 + s0;
        l1 = l1 * al1 + s1;
#pragma unroll
        for (int nt = 0; nt < 8; nt++) {
            oacc[nt][0] *= al0; oacc[nt][1] *= al0;
            oacc[nt][2] *= al1; oacc[nt][3] *= al1;
        }

        // O += P V : P A-fragments built directly from sacc (R7 order)
#pragma unroll
        for (int ks = 0; ks < 4; ks++) {
            unsigned pah[4], pal[4];
            split_pair(sacc[2 * ks][0],     sacc[2 * ks][1],     pah[0], pal[0]);
            split_pair(sacc[2 * ks][2],     sacc[2 * ks][3],     pah[1], pal[1]);
            split_pair(sacc[2 * ks + 1][0], sacc[2 * ks + 1][1], pah[2], pal[2]);
            split_pair(sacc[2 * ks + 1][2], sacc[2 * ks + 1][3], pah[3], pal[3]);
            int pb = ks * 8;
#pragma unroll
            for (int j = 0; j < 4; j++) {
                unsigned vh4[4], vl4[4];
                unsigned vo = kBase + 2 * KVT * 4 + (j * 16 * KLD + pb) * 4;
                ldsm4(vh4, vo);
                ldsm4(vl4, vo + KVT * 4);
                mma_bf16(oacc[2 * j],     pah, vh4[0], vh4[1]);
                mma_bf16(oacc[2 * j],     pah, vl4[0], vl4[1]);
                mma_bf16(oacc[2 * j],     pal, vh4[0], vh4[1]);
                mma_bf16(oacc[2 * j + 1], pah, vh4[2], vh4[3]);
                mma_bf16(oacc[2 * j + 1], pah, vl4[2], vl4[3]);
                mma_bf16(oacc[2 * j + 1], pal, vh4[2], vh4[3]);
            }
        }
        // no trailing barrier (4-deep ring; see GEMM comment)
    }

    float inv0 = 1.f / (l0 * 32.f);
    float inv1 = 1.f / (l1 * 32.f);
    int n0r = q0 + wrow + g;
    int n1r = n0r + 8;
    int dr0 = h * 128 + (n0r >> 4), dc0 = (n0r & 15) * 64;
    int dr1 = h * 128 + (n1r >> 4), dc1 = (n1r & 15) * 64;
#pragma unroll
    for (int nt = 0; nt < 8; nt++) {
        int c = nt * 8 + 2 * q;
        float2 qr0 = *(const float2*)(g_q + (size_t)n0r * DIM + c0 + c);
        float2 qr1 = *(const float2*)(g_q + (size_t)n1r * DIM + c0 + c);
        float o0x = qr0.x + oacc[nt][0] * inv0;
        float o0y = qr0.y + oacc[nt][1] * inv0;
        float o1x = qr1.x + oacc[nt][2] * inv1;
        float o1y = qr1.y + oacc[nt][3] * inv1;
        *(float2*)(g_o + (size_t)dr0 * DIM + dc0 + c) = make_float2(o0x, o0y);
        *(float2*)(g_o + (size_t)dr1 * DIM + dc1 + c) = make_float2(o1x, o1y);
        unsigned hh, ll;
        split_pair(o0x, o0y, hh, ll);
        g_ohi[(size_t)dr0 * PD + (dc0 + c) / 2] = hh;
        g_olo[(size_t)dr0 * PD + (dc0 + c) / 2] = ll;
        split_pair(o1x, o1y, hh, ll);
        g_ohi[(size_t)dr1 * PD + (dc1 + c) / 2] = hh;
        g_olo[(size_t)dr1 * PD + (dc1 + c) / 2] = ll;
    }
}

// ---------------------------------------------------------------------------
extern "C" void kernel_launch(void* const* d_in, const int* in_sizes, int n_in,
                              void* d_out, int out_size)
{
    const float* Q  = (const float*)d_in[0];
    const float* K  = (const float*)d_in[1];
    const float* Wq = (const float*)d_in[2];
    const float* bq = (const float*)d_in[3];
    const float* Wk = (const float*)d_in[4];
    const float* bk = (const float*)d_in[5];
    const float* Wv = (const float*)d_in[6];
    const float* bv = (const float*)d_in[7];
    const float* Wo = (const float*)d_in[8];
    const float* bo = (const float*)d_in[9];
    float* out = (float*)d_out;

    cudaFuncSetAttribute(gemm_all,    cudaFuncAttributeMaxDynamicSharedMemorySize, GEMM_SMEM);
    cudaFuncSetAttribute(attn_bf16x2, cudaFuncAttributeMaxDynamicSharedMemorySize, ATTN_SMEM);

    pack_all<<<dim3(SEGP / 256, 8), 256>>>(Q, K, Wq, Wk, Wv, Wo);
    gemm_all<<<dim3(DIM / 128, NQ / 128, 3), 256, GEMM_SMEM>>>(bq, bk, bv, bo, out, 0);
    attn_bf16x2<<<dim3(NQ / 128, NHEAD), 256, ATTN_SMEM>>>();
    gemm_all<<<dim3(DIM / 128, NQ / 128, 1), 256, GEMM_SMEM>>>(bq, bk, bv, bo, out, 1);
}